// round 3
// baseline (speedup 1.0000x reference)
#include <cuda_runtime.h>
#include <math.h>

#define Bq   8
#define Nseq 512
#define Edim 256
#define Hh   8
#define DKd  32
#define SCALE 0.17677669529663687f   // 1/sqrt(32)

// ---------------- scratch (device globals; zero-initialized) ------------------
__device__ float g_q[Bq*Hh*Nseq*DKd];
__device__ float g_k[Bq*Hh*Nseq*DKd];
__device__ float g_v[Bq*Hh*Nseq*DKd];
__device__ float g_x[Bq*Nseq*3*Edim];        // concat attn outputs (B,N,768)
__device__ float g_h1[Bq*Nseq*Edim];
__device__ float g_wcat[3*Edim*Edim];        // [Wo@Ws1_bar] stacked (768x256)
__device__ float g_bfull[Edim];              // bs1 + sum bo@Ws1_bar
__device__ float g_zero[Edim];               // stays zero

// ---------------- packed f32x2 helpers ----------------------------------------
__device__ __forceinline__ unsigned long long pk2(float lo, float hi) {
    unsigned long long r;
    asm("mov.b64 %0, {%1, %2};" : "=l"(r)
        : "r"(__float_as_uint(lo)), "r"(__float_as_uint(hi)));
    return r;
}
__device__ __forceinline__ void fma2(unsigned long long& d,
                                     unsigned long long a, unsigned long long b) {
    asm("fma.rn.f32x2 %0, %1, %2, %3;" : "=l"(d) : "l"(a), "l"(b), "l"(d));
}
__device__ __forceinline__ float2 upk(unsigned long long v) {
    unsigned int lo, hi;
    asm("mov.b64 {%0, %1}, %2;" : "=r"(lo), "=r"(hi) : "l"(v));
    return make_float2(__uint_as_float(lo), __uint_as_float(hi));
}

// ---------------- 128x64-tile fp32x2 GEMM, double-buffered, z-batched ---------
__global__ __launch_bounds__(256) void gemm128(
    const float* __restrict__ A0, const float* __restrict__ A1, const float* __restrict__ A2,
    const float* __restrict__ W0, const float* __restrict__ W1, const float* __restrict__ W2,
    const float* __restrict__ bias0, const float* __restrict__ bias1, const float* __restrict__ bias2,
    float* __restrict__ C0, float* __restrict__ C1, float* __restrict__ C2,
    int Kd, int ldw, int ldc, int do_relu, int headsplit)
{
    const int z = blockIdx.z;
    const float* A    = (z == 0) ? A0 : (z == 1) ? A1 : A2;
    const float* W    = (z == 0) ? W0 : (z == 1) ? W1 : W2;
    const float* bias = (z == 0) ? bias0 : (z == 1) ? bias1 : bias2;
    float*       C    = (z == 0) ? C0 : (z == 1) ? C1 : C2;

    __shared__ float As[2][16][136];   // k-major A tile
    __shared__ float Ws[2][16][68];

    const int m0 = blockIdx.x << 7;
    const int n0 = blockIdx.y << 6;
    const int tid = threadIdx.x;
    const int tx = tid & 15, ty = tid >> 4;

    const int ar = tid >> 1;           // A row within tile
    const int ac = (tid & 1) << 3;     // A k-offset
    const int wr = tid >> 4;
    const int wc = (tid & 15) << 2;

    const float* Aptr = A + (size_t)(m0 + ar) * Kd + ac;
    const float* Wptr = W + (size_t)wr * ldw + n0 + wc;

    float4 a0p = *(const float4*)(Aptr);
    float4 a1p = *(const float4*)(Aptr + 4);
    float4 wp  = *(const float4*)(Wptr);

    unsigned long long acc[8][2] = {};

    // store first tile
    As[0][ac+0][ar] = a0p.x; As[0][ac+1][ar] = a0p.y;
    As[0][ac+2][ar] = a0p.z; As[0][ac+3][ar] = a0p.w;
    As[0][ac+4][ar] = a1p.x; As[0][ac+5][ar] = a1p.y;
    As[0][ac+6][ar] = a1p.z; As[0][ac+7][ar] = a1p.w;
    *(float4*)&Ws[0][wr][wc] = wp;
    __syncthreads();

    const int nk = Kd >> 4;
    for (int kt = 0; kt < nk; kt++) {
        const int cur = kt & 1, nxt = cur ^ 1;
        if (kt + 1 < nk) {
            a0p = *(const float4*)(Aptr + (kt+1)*16);
            a1p = *(const float4*)(Aptr + (kt+1)*16 + 4);
            wp  = *(const float4*)(Wptr + (size_t)(kt+1)*16*ldw);
        }
        #pragma unroll
        for (int kk = 0; kk < 16; kk++) {
            float4 aA = *(const float4*)&As[cur][kk][ty << 3];
            float4 aB = *(const float4*)&As[cur][kk][(ty << 3) + 4];
            double2 wv = *(const double2*)&Ws[cur][kk][tx << 2];
            unsigned long long w01 = __double_as_longlong(wv.x);
            unsigned long long w23 = __double_as_longlong(wv.y);
            float a[8] = {aA.x, aA.y, aA.z, aA.w, aB.x, aB.y, aB.z, aB.w};
            #pragma unroll
            for (int i = 0; i < 8; i++) {
                unsigned long long ad = pk2(a[i], a[i]);
                fma2(acc[i][0], ad, w01);
                fma2(acc[i][1], ad, w23);
            }
        }
        if (kt + 1 < nk) {
            As[nxt][ac+0][ar] = a0p.x; As[nxt][ac+1][ar] = a0p.y;
            As[nxt][ac+2][ar] = a0p.z; As[nxt][ac+3][ar] = a0p.w;
            As[nxt][ac+4][ar] = a1p.x; As[nxt][ac+5][ar] = a1p.y;
            As[nxt][ac+6][ar] = a1p.z; As[nxt][ac+7][ar] = a1p.w;
            *(float4*)&Ws[nxt][wr][wc] = wp;
        }
        __syncthreads();
    }

    const int col0 = n0 + (tx << 2);
    float4 b4 = *(const float4*)&bias[col0];
    #pragma unroll
    for (int i = 0; i < 8; i++) {
        int m = m0 + (ty << 3) + i;
        float2 u0 = upk(acc[i][0]);
        float2 u1 = upk(acc[i][1]);
        float4 r;
        r.x = u0.x + b4.x; r.y = u0.y + b4.y;
        r.z = u1.x + b4.z; r.w = u1.y + b4.w;
        if (do_relu) {
            r.x = fmaxf(r.x, 0.f); r.y = fmaxf(r.y, 0.f);
            r.z = fmaxf(r.z, 0.f); r.w = fmaxf(r.w, 0.f);
        }
        if (headsplit) {
            int b = m >> 9, n = m & 511;
            int h = col0 >> 5, d = col0 & 31;
            *(float4*)&C[(((size_t)(b*Hh + h))*Nseq + n)*DKd + d] = r;
        } else {
            *(float4*)&C[(size_t)m * ldc + col0] = r;
        }
    }
}

// ---------------- bias fold: bfull = bs1 + sum_bar bo @ Ws1_bar ---------------
__global__ void bias_fold(const float* __restrict__ bo, const float* __restrict__ Ws1,
                          const float* __restrict__ bs1, float* __restrict__ bfull)
{
    int n = threadIdx.x;
    float s = bs1[n];
    #pragma unroll 8
    for (int r = 0; r < 3*Edim; r++)
        s += bo[r & (Edim-1)] * Ws1[(size_t)r * Edim + n];
    bfull[n] = s;
}

// ---------------- fused multi-bar attention (f32x2 packed) --------------------
__global__ __launch_bounds__(256) void attn_kernel(
    const float* __restrict__ Q, const float* __restrict__ K, const float* __restrict__ V,
    const float* __restrict__ dist, const int* __restrict__ mask,
    const float* __restrict__ cw1, const float* __restrict__ cb1,
    const float* __restrict__ cw2, const float* __restrict__ cb2,
    float* __restrict__ xcat)
{
    __shared__ float Qs[64][33];            // row-major (scalar broadcast reads)
    __shared__ float Kst[32][68];           // d-major K tile
    __shared__ float Vt[32][68];            // d-major V tile
    __shared__ float Es[64][68];            // exp(scores)
    __shared__ unsigned char Rs[64][68];    // region codes

    const int qt = blockIdx.x;
    const int bh = blockIdx.y;
    const int b = bh >> 3, h = bh & 7;
    const int q0 = qt << 6;
    const int tid = threadIdx.x;
    const int tx = tid & 15, ty = tid >> 4;

    float cw1r[8], cb1r[8], cw2r[8];
    #pragma unroll
    for (int t = 0; t < 8; t++) {
        cw1r[t] = cw1[t]; cb1r[t] = cb1[t]; cw2r[t] = cw2[h*8 + t];
    }
    const float cb2h = cb2[h];

    const size_t headbase = ((size_t)(b*Hh + h)) * Nseq * DKd;

    const float* Qb = Q + headbase + (size_t)q0 * DKd;
    for (int t = tid; t < 64*32; t += 256) Qs[t >> 5][t & 31] = Qb[t];

    unsigned long long o2[3][4][2] = {};    // packed (even-j, odd-j) partials
    float lsum[3][4] = {};

    for (int kt = 0; kt < 8; kt++) {
        const int k0 = kt << 6;
        const float* Kb = K + headbase + (size_t)k0 * DKd;
        const float* Vb = V + headbase + (size_t)k0 * DKd;
        __syncthreads();
        for (int t = tid; t < 64*32; t += 256) {
            Kst[t & 31][t >> 5] = Kb[t];
            Vt[t & 31][t >> 5]  = Vb[t];
        }
        __syncthreads();

        // ---- S = Q K^T, packed over j-pairs ----
        unsigned long long s2[4][2] = {};
        #pragma unroll
        for (int d = 0; d < 32; d++) {
            double2 kd = *(const double2*)&Kst[d][tx << 2];
            unsigned long long k01 = __double_as_longlong(kd.x);
            unsigned long long k23 = __double_as_longlong(kd.y);
            #pragma unroll
            for (int i = 0; i < 4; i++) {
                float a = Qs[ty*4 + i][d];
                unsigned long long ad = pk2(a, a);
                fma2(s2[i][0], ad, k01);
                fma2(s2[i][1], ad, k23);
            }
        }

        // ---- dist conv + mask -> e, region; lsum; stage to smem ----
        #pragma unroll
        for (int i = 0; i < 4; i++) {
            int qi = q0 + ty*4 + i;
            const float* drow = dist + ((size_t)b*Nseq + qi) * Nseq + k0;
            const int*   mrow = mask + ((size_t)b*Nseq + qi) * Nseq + k0;
            float4 d4 = *(const float4*)&drow[tx << 2];
            int4   m4 = *(const int4*)&mrow[tx << 2];
            float dv[4] = {d4.x, d4.y, d4.z, d4.w};
            int   mv[4] = {m4.x, m4.y, m4.z, m4.w};
            float2 su0 = upk(s2[i][0]);
            float2 su1 = upk(s2[i][1]);
            float sj[4] = {su0.x, su0.y, su1.x, su1.y};
            float e[4];
            unsigned int rcode = 0;
            #pragma unroll
            for (int j = 0; j < 4; j++) {
                int kj = k0 + tx*4 + j;
                float d = dv[j];
                float conv = cb2h;
                #pragma unroll
                for (int t = 0; t < 8; t++)
                    conv += cw2r[t] * fmaxf(fmaf(d, cw1r[t], cb1r[t]), 0.f);
                float sv = sj[j] * SCALE * conv;
                float ev = (mv[j] == 0) ? 0.f : __expf(sv);
                e[j] = ev;
                unsigned int r = (qi == 0 || kj == 0) ? 0u
                               : (d < 0.3f) ? 0u : (d < 0.7f) ? 1u : 2u;
                rcode |= r << (j * 8);
                lsum[2][i] += ev;
                lsum[1][i] += (r < 2u) ? ev : 0.f;
                lsum[0][i] += (r < 1u) ? ev : 0.f;
            }
            *(float4*)&Es[ty*4 + i][tx << 2] = make_float4(e[0], e[1], e[2], e[3]);
            *(unsigned int*)&Rs[ty*4 + i][tx << 2] = rcode;
        }
        __syncthreads();

        // ---- single-pass PV, all bars, packed j-pairs ----
        const int d0 = tx << 1;
        #pragma unroll
        for (int jg = 0; jg < 16; jg++) {
            double2 v0d = *(const double2*)&Vt[d0][jg << 2];
            double2 v1d = *(const double2*)&Vt[d0 + 1][jg << 2];
            unsigned long long v0_01 = __double_as_longlong(v0d.x);
            unsigned long long v0_23 = __double_as_longlong(v0d.y);
            unsigned long long v1_01 = __double_as_longlong(v1d.x);
            unsigned long long v1_23 = __double_as_longlong(v1d.y);
            #pragma unroll
            for (int i = 0; i < 4; i++) {
                float4 e4 = *(const float4*)&Es[ty*4 + i][jg << 2];
                unsigned int ru = *(const unsigned int*)&Rs[ty*4 + i][jg << 2];
                unsigned int r0 = ru & 0xffu, r1 = (ru >> 8) & 0xffu;
                unsigned int rr2 = (ru >> 16) & 0xffu, r3 = ru >> 24;
                unsigned long long p2_01 = pk2(e4.x, e4.y);
                unsigned long long p2_23 = pk2(e4.z, e4.w);
                unsigned long long p1_01 = pk2(r0 < 2u ? e4.x : 0.f, r1 < 2u ? e4.y : 0.f);
                unsigned long long p1_23 = pk2(rr2 < 2u ? e4.z : 0.f, r3 < 2u ? e4.w : 0.f);
                unsigned long long p0_01 = pk2(r0 < 1u ? e4.x : 0.f, r1 < 1u ? e4.y : 0.f);
                unsigned long long p0_23 = pk2(rr2 < 1u ? e4.z : 0.f, r3 < 1u ? e4.w : 0.f);
                fma2(o2[2][i][0], p2_01, v0_01); fma2(o2[2][i][0], p2_23, v0_23);
                fma2(o2[2][i][1], p2_01, v1_01); fma2(o2[2][i][1], p2_23, v1_23);
                fma2(o2[1][i][0], p1_01, v0_01); fma2(o2[1][i][0], p1_23, v0_23);
                fma2(o2[1][i][1], p1_01, v1_01); fma2(o2[1][i][1], p1_23, v1_23);
                fma2(o2[0][i][0], p0_01, v0_01); fma2(o2[0][i][0], p0_23, v0_23);
                fma2(o2[0][i][1], p0_01, v1_01); fma2(o2[0][i][1], p0_23, v1_23);
            }
        }
    }

    // ---- reduce row sums across the 16 lanes owning each row ----
    #pragma unroll
    for (int bar = 0; bar < 3; bar++)
        #pragma unroll
        for (int i = 0; i < 4; i++) {
            float v = lsum[bar][i];
            #pragma unroll
            for (int off = 1; off < 16; off <<= 1)
                v += __shfl_xor_sync(0xffffffffu, v, off);
            lsum[bar][i] = v;
        }

    // ---- normalize + write concat layout (B,N, bar*256 + h*32 + d) ----
    #pragma unroll
    for (int bar = 0; bar < 3; bar++)
        #pragma unroll
        for (int i = 0; i < 4; i++) {
            int qi = q0 + ty*4 + i;
            float rl = 1.f / lsum[bar][i];
            float2 u0 = upk(o2[bar][i][0]);
            float2 u1 = upk(o2[bar][i][1]);
            size_t base = ((size_t)b*Nseq + qi) * (3*Edim) + bar*Edim + h*DKd + (tx << 1);
            xcat[base]     = (u0.x + u0.y) * rl;
            xcat[base + 1] = (u1.x + u1.y) * rl;
        }
}

// ---------------- host launcher ----------------------------------------------
extern "C" void kernel_launch(void* const* d_in, const int* in_sizes, int n_in,
                              void* d_out, int out_size)
{
    const float* query = (const float*)d_in[0];
    const float* key   = (const float*)d_in[1];
    const float* value = (const float*)d_in[2];
    const float* dist  = (const float*)d_in[3];
    const int*   mask  = (const int*)d_in[4];
    const float* Wq = (const float*)d_in[5];
    const float* bq = (const float*)d_in[6];
    const float* Wk = (const float*)d_in[7];
    const float* bk = (const float*)d_in[8];
    const float* Wv = (const float*)d_in[9];
    const float* bv = (const float*)d_in[10];
    const float* Wo = (const float*)d_in[11];
    const float* bo = (const float*)d_in[12];
    const float* cw1 = (const float*)d_in[13];
    const float* cb1 = (const float*)d_in[14];
    const float* cw2 = (const float*)d_in[15];
    const float* cb2 = (const float*)d_in[16];
    const float* Ws1 = (const float*)d_in[17];
    const float* bs1 = (const float*)d_in[18];
    const float* Ws2 = (const float*)d_in[19];
    const float* bs2 = (const float*)d_in[20];
    float* out = (float*)d_out;

    float *q_p, *k_p, *v_p, *x_p, *h1_p, *wcat_p, *bfull_p, *zero_p;
    cudaGetSymbolAddress((void**)&q_p,    g_q);
    cudaGetSymbolAddress((void**)&k_p,    g_k);
    cudaGetSymbolAddress((void**)&v_p,    g_v);
    cudaGetSymbolAddress((void**)&x_p,    g_x);
    cudaGetSymbolAddress((void**)&h1_p,   g_h1);
    cudaGetSymbolAddress((void**)&wcat_p, g_wcat);
    cudaGetSymbolAddress((void**)&bfull_p,g_bfull);
    cudaGetSymbolAddress((void**)&zero_p, g_zero);

    const int M = Bq * Nseq;          // 4096
    dim3 blk(256);

    // precompute Wcat = [Wo @ Ws1_bar] (768x256) and folded bias
    {
        dim3 grid(Edim / 128, Edim / 64, 3);
        gemm128<<<grid, blk>>>(Wo, Wo, Wo,
                               Ws1, Ws1 + Edim*Edim, Ws1 + 2*Edim*Edim,
                               zero_p, zero_p, zero_p,
                               wcat_p, wcat_p + Edim*Edim, wcat_p + 2*Edim*Edim,
                               Edim, Edim, Edim, 0, 0);
        bias_fold<<<1, Edim>>>(bo, Ws1, bs1, bfull_p);
    }

    // QKV projections -> (B,H,N,DK), z-batched
    {
        dim3 grid(M / 128, Edim / 64, 3);
        gemm128<<<grid, blk>>>(query, key, value,
                               Wq, Wk, Wv,
                               bq, bk, bv,
                               q_p, k_p, v_p,
                               Edim, Edim, 0, 0, 1);
    }

    // fused multi-bar attention -> concat layout g_x (B,N,768)
    {
        dim3 grid(Nseq / 64, Bq * Hh);
        attn_kernel<<<grid, blk>>>(q_p, k_p, v_p, dist, mask,
                                   cw1, cb1, cw2, cb2, x_p);
    }

    // h1 = relu(xcat @ Wcat + bfull)   (replaces 3x Wo GEMMs + Ws1 GEMM)
    {
        dim3 grid(M / 128, Edim / 64, 1);
        gemm128<<<grid, blk>>>(x_p, x_p, x_p, wcat_p, wcat_p, wcat_p,
                               bfull_p, bfull_p, bfull_p,
                               h1_p, h1_p, h1_p, 3*Edim, Edim, Edim, 1, 0);
    }

    // out = h1 @ Ws2 + bs2
    {
        dim3 grid(M / 128, Edim / 64, 1);
        gemm128<<<grid, blk>>>(h1_p, h1_p, h1_p, Ws2, Ws2, Ws2, bs2, bs2, bs2,
                               out, out, out, Edim, Edim, Edim, 0, 0);
    }
}